// round 1
// baseline (speedup 1.0000x reference)
#include <cuda_runtime.h>

// Problem constants
#define Hn 128
#define Vn 256
#define Bn 4
#define BV 1024            // B*V node count
#define NE 262144          // B*V*V edge count
#define K1_BLOCKS 1024     // one block per (b,i)

// ------------------------- device scratch (no allocations allowed) -------
__device__ float g_Uh[BV * Hn];
__device__ float g_Vh[BV * Hn];
__device__ float g_Ah[BV * Hn];
__device__ float g_Bh[BV * Hn];
__device__ float g_hpre[BV * Hn];          // Uh + masked aggregation (pre-BN h)
__device__ float g_ps[K1_BLOCKS * Hn];     // per-block per-channel sum of e_new
__device__ float g_ps2[K1_BLOCKS * Hn];    // per-block per-channel sum of e_new^2
__device__ float g_rs_e[Hn], g_ofs_e[Hn];  // gamma*rsqrt(var+eps), beta - mu*rs
__device__ float g_rs_h[Hn], g_ofs_h[Hn];

__device__ __forceinline__ float sigmoidf_(float v) {
    return 1.0f / (1.0f + __expf(-v));
}

// ------------------------- K0: node linears Uh/Vh/Ah/Bh -------------------
// grid 64 x 256 threads, 16 rows per block. 67 MFMA total: negligible.
__global__ void k_node_lin(const float* __restrict__ h,
                           const float* __restrict__ Uw, const float* __restrict__ Ub,
                           const float* __restrict__ Vw, const float* __restrict__ Vb,
                           const float* __restrict__ Aw, const float* __restrict__ Ab,
                           const float* __restrict__ Bw, const float* __restrict__ Bb) {
    __shared__ float hs[16 * Hn];
    int tid = threadIdx.x;
    int row0 = blockIdx.x * 16;
    for (int idx = tid; idx < 16 * Hn; idx += 256)
        hs[idx] = h[(size_t)row0 * Hn + idx];
    __syncthreads();
    const float* Ws[4] = {Uw, Vw, Aw, Bw};
    const float* bs[4] = {Ub, Vb, Ab, Bb};
    float* outs[4];
    outs[0] = g_Uh; outs[1] = g_Vh; outs[2] = g_Ah; outs[3] = g_Bh;
    for (int p = 0; p < 2; p++) {
        int cid = tid + 256 * p;      // 0..511 -> (matrix, out-channel)
        int m = cid >> 7;
        int o = cid & 127;
        const float* W = Ws[m] + (size_t)o * Hn;
        float acc[16];
        #pragma unroll
        for (int r = 0; r < 16; r++) acc[r] = 0.f;
        for (int k = 0; k < Hn; k += 4) {
            float4 w = *(const float4*)(W + k);
            #pragma unroll
            for (int r = 0; r < 16; r++) {
                acc[r] += hs[r * Hn + k] * w.x + hs[r * Hn + k + 1] * w.y +
                          hs[r * Hn + k + 2] * w.z + hs[r * Hn + k + 3] * w.w;
            }
        }
        float bias = bs[m][o];
        float* op = outs[m] + (size_t)row0 * Hn + o;
        #pragma unroll
        for (int r = 0; r < 16; r++) op[(size_t)r * Hn] = acc[r] + bias;
    }
}

// ------------------------- K1: fused main kernel --------------------------
// One block per (b,i). Computes e_new[b,i,:,:] (Ce GEMM + adds), writes it to
// out_e (scratch for later BN pass), accumulates:
//   - masked sigmoid-gated Vh aggregation -> g_hpre
//   - per-channel BN partial sums of e_new -> g_ps / g_ps2
//   - pa (edge-probability) * diff -> out_x directly (no BN on x)
__global__ void __launch_bounds__(256, 2)
k_main(const float* __restrict__ e, const float* __restrict__ x,
       const int* __restrict__ graph,
       const float* __restrict__ Cw, const float* __restrict__ Cb,
       const float* __restrict__ dwv, const float* __restrict__ dbv,
       const float* __restrict__ ewv, const float* __restrict__ ebp,
       const float* __restrict__ cp,
       float* __restrict__ out_e, float* __restrict__ out_x) {
    extern __shared__ float sm[];
    float* sCw   = sm;               // 16384 : Cw transposed [k][o]
    float* se    = sCw + 16384;      // 8192  : e tile [j_local][k] (64x128)
    float* sBhdb = se + 8192;        // 128   : Bh[b,i,:] + db + Cb
    float* sdw   = sBhdb + 128;      // 128
    float* sew   = sdw + 128;        // 128
    float* shacc = sew + 128;        // 128
    float* ssum  = shacc + 128;      // 128
    float* ssum2 = ssum + 128;       // 128
    float* sdist = ssum2 + 128;      // 64
    float* sdfx  = sdist + 64;       // 64
    float* sdfy  = sdfx + 64;        // 64
    float* spa   = sdfy + 64;        // 64
    int*   sg    = (int*)(spa + 64); // 64
    // total 25664 floats = 102656 B

    int tid = threadIdx.x;
    int bid = blockIdx.x;            // = b*V + i
    int b = bid >> 8;

    // transpose Cw into smem: sCw[k][o] = Cw[o][k]
    for (int idx = tid; idx < 4096; idx += 256) {
        int o = idx & 127, kq = idx >> 7;
        float4 w = *(const float4*)(Cw + (size_t)o * Hn + kq * 4);
        sCw[(kq * 4 + 0) * Hn + o] = w.x;
        sCw[(kq * 4 + 1) * Hn + o] = w.y;
        sCw[(kq * 4 + 2) * Hn + o] = w.z;
        sCw[(kq * 4 + 3) * Hn + o] = w.w;
    }
    if (tid < 128) {
        sBhdb[tid] = g_Bh[(size_t)bid * Hn + tid] + dbv[tid] + Cb[tid];
        sdw[tid]   = dwv[tid];
        sew[tid]   = ewv[tid];
        shacc[tid] = 0.f; ssum[tid] = 0.f; ssum2[tid] = 0.f;
    }
    float xi = x[bid * 2], yi = x[bid * 2 + 1];
    float eb_s = ebp[0], c_s = cp[0];

    int h0 = (tid & 15) * 8;    // output-channel group (16 groups x 8)
    int j0 = (tid >> 4) * 4;    // j group within tile    (16 groups x 4)

    float macc[8], ps[8], ps2[8];
    #pragma unroll
    for (int u = 0; u < 8; u++) { macc[u] = 0.f; ps[u] = 0.f; ps2[u] = 0.f; }
    float xax = 0.f, xay = 0.f;

    for (int jt = 0; jt < 4; jt++) {
        int jbase = jt * 64;
        __syncthreads();   // protect se / spa / sdist from previous tile readers
        {
            const float4* src = (const float4*)(e + ((size_t)bid * Vn + jbase) * Hn);
            float4* dst = (float4*)se;
            for (int idx = tid; idx < 2048; idx += 256) dst[idx] = __ldg(src + idx);
        }
        if (tid < 64) {
            int jg = jbase + tid;
            float dx = xi - x[(b * Vn + jg) * 2];
            float dy = yi - x[(b * Vn + jg) * 2 + 1];
            float d2 = dx * dx + dy * dy;
            sdist[tid] = d2 > 0.f ? sqrtf(d2) : 0.f;
            sdfx[tid] = dx; sdfy[tid] = dy;
            sg[tid] = graph[(size_t)bid * Vn + jg];
            spa[tid] = 0.f;
        }
        __syncthreads();

        // ---- Ce GEMM: 64j x 128h tile, thread tile 4j x 8h ----
        float acc[4][8];
        #pragma unroll
        for (int jj = 0; jj < 4; jj++)
            #pragma unroll
            for (int u = 0; u < 8; u++) acc[jj][u] = 0.f;

        #pragma unroll 4
        for (int k = 0; k < Hn; k++) {
            float4 c0 = *(const float4*)(sCw + k * Hn + h0);
            float4 c1 = *(const float4*)(sCw + k * Hn + h0 + 4);
            float cw[8] = {c0.x, c0.y, c0.z, c0.w, c1.x, c1.y, c1.z, c1.w};
            #pragma unroll
            for (int jj = 0; jj < 4; jj++) {
                float evk = se[(j0 + jj) * Hn + k];
                #pragma unroll
                for (int u = 0; u < 8; u++) acc[jj][u] += evk * cw[u];
            }
        }

        // ---- fused epilogue ----
        #pragma unroll
        for (int jj = 0; jj < 4; jj++) {
            int jl = j0 + jj;
            int jg = jbase + jl;
            size_t nrow = ((size_t)(b * Vn + jg)) * Hn + h0;
            float4 a0 = __ldg((const float4*)(g_Ah + nrow));
            float4 a1 = __ldg((const float4*)(g_Ah + nrow) + 1);
            float4 v0 = __ldg((const float4*)(g_Vh + nrow));
            float4 v1 = __ldg((const float4*)(g_Vh + nrow) + 1);
            float av[8] = {a0.x, a0.y, a0.z, a0.w, a1.x, a1.y, a1.z, a1.w};
            float vv[8] = {v0.x, v0.y, v0.z, v0.w, v1.x, v1.y, v1.z, v1.w};
            float dist = sdist[jl];
            bool keep = (sg[jl] != 1);
            float pdj = 0.f;
            float evv[8];
            #pragma unroll
            for (int u = 0; u < 8; u++) {
                float t = acc[jj][u] + av[u] + sBhdb[h0 + u] + dist * sdw[h0 + u];
                evv[u] = t;
                ps[u] += t; ps2[u] += t * t;
                float gsig = sigmoidf_(t);
                if (keep) macc[u] += gsig * vv[u];
                pdj += t * sew[h0 + u];
            }
            atomicAdd(&spa[jl], pdj);
            size_t ob = ((size_t)bid * Vn + jg) * Hn + h0;
            *(float4*)(out_e + ob)     = make_float4(evv[0], evv[1], evv[2], evv[3]);
            *(float4*)(out_e + ob + 4) = make_float4(evv[4], evv[5], evv[6], evv[7]);
        }
        __syncthreads();
        if (tid < 64) {
            float paj = sigmoidf_(spa[tid] + eb_s);
            xax += paj * sdfx[tid];
            xay += paj * sdfy[tid];
        }
    }

    // ---- block-level reductions ----
    #pragma unroll
    for (int u = 0; u < 8; u++) {
        atomicAdd(&shacc[h0 + u], macc[u]);
        atomicAdd(&ssum[h0 + u], ps[u]);
        atomicAdd(&ssum2[h0 + u], ps2[u]);
    }
    if (tid < 64) { sdfx[tid] = xax; sdfy[tid] = xay; }
    __syncthreads();
    if (tid == 0) {
        float sx = 0.f, sy = 0.f;
        for (int t = 0; t < 64; t++) { sx += sdfx[t]; sy += sdfy[t]; }
        out_x[bid * 2]     = xi + c_s * sx;
        out_x[bid * 2 + 1] = yi + c_s * sy;
    }
    if (tid < 128) {
        g_ps[(size_t)bid * Hn + tid]  = ssum[tid];
        g_ps2[(size_t)bid * Hn + tid] = ssum2[tid];
        g_hpre[(size_t)bid * Hn + tid] = g_Uh[(size_t)bid * Hn + tid] + shacc[tid];
    }
}

// ------------------------- K2: BN statistics (deterministic) --------------
__global__ void k_stats(const float* __restrict__ gamma_h, const float* __restrict__ beta_h,
                        const float* __restrict__ gamma_e, const float* __restrict__ beta_e) {
    int ch = threadIdx.x;   // 128 threads
    double s = 0.0, s2 = 0.0;
    for (int p = 0; p < K1_BLOCKS; p++) {
        s  += (double)g_ps[(size_t)p * Hn + ch];
        s2 += (double)g_ps2[(size_t)p * Hn + ch];
    }
    float mu  = (float)(s  * (1.0 / (double)NE));
    float var = (float)(s2 * (1.0 / (double)NE)) - mu * mu;
    float rs = gamma_e[ch] * rsqrtf(var + 1e-5f);
    g_rs_e[ch] = rs;
    g_ofs_e[ch] = beta_e[ch] - mu * rs;

    double sh = 0.0, sh2 = 0.0;
    for (int r = 0; r < BV; r++) {
        float v = g_hpre[(size_t)r * Hn + ch];
        sh += (double)v; sh2 += (double)v * (double)v;
    }
    float muh  = (float)(sh  * (1.0 / (double)BV));
    float varh = (float)(sh2 * (1.0 / (double)BV)) - muh * muh;
    float rsh = gamma_h[ch] * rsqrtf(varh + 1e-5f);
    g_rs_h[ch] = rsh;
    g_ofs_h[ch] = beta_h[ch] - muh * rsh;
}

// ------------------------- K3h: h residual + BN + ReLU --------------------
__global__ void k_h_out(const float* __restrict__ h, float* __restrict__ out_h) {
    int idx = blockIdx.x * 256 + threadIdx.x;   // 512*256 = 131072 exact
    int ch = idx & 127;
    float v = fmaf(g_hpre[idx], g_rs_h[ch], g_ofs_h[ch]);
    out_h[idx] = h[idx] + fmaxf(v, 0.f);
}

// ------------------------- K3e: e residual + BN + ReLU (in place) ---------
__global__ void k_e_out(const float4* __restrict__ e, float4* __restrict__ oe) {
    int idx = blockIdx.x * 256 + threadIdx.x;   // 32768*256 = 8388608 float4 exact
    int c4 = idx & 31;                          // 128 channels / 4 per float4
    float4 rs = *(const float4*)(g_rs_e + 4 * c4);
    float4 of = *(const float4*)(g_ofs_e + 4 * c4);
    float4 en = oe[idx];                        // e_new scratch
    float4 ev = __ldg(e + idx);
    ev.x += fmaxf(fmaf(en.x, rs.x, of.x), 0.f);
    ev.y += fmaxf(fmaf(en.y, rs.y, of.y), 0.f);
    ev.z += fmaxf(fmaf(en.z, rs.z, of.z), 0.f);
    ev.w += fmaxf(fmaf(en.w, rs.w, of.w), 0.f);
    oe[idx] = ev;
}

// ------------------------- launcher ---------------------------------------
extern "C" void kernel_launch(void* const* d_in, const int* in_sizes, int n_in,
                              void* d_out, int out_size) {
    const float* h     = (const float*)d_in[0];
    const float* e     = (const float*)d_in[1];
    const float* x     = (const float*)d_in[2];
    const int*   graph = (const int*)d_in[3];
    const float* Uw = (const float*)d_in[4],  *Ub = (const float*)d_in[5];
    const float* Vw = (const float*)d_in[6],  *Vb = (const float*)d_in[7];
    const float* Aw = (const float*)d_in[8],  *Ab = (const float*)d_in[9];
    const float* Bw = (const float*)d_in[10], *Bb = (const float*)d_in[11];
    const float* Cw = (const float*)d_in[12], *Cb = (const float*)d_in[13];
    const float* dwv = (const float*)d_in[14], *dbv = (const float*)d_in[15];
    const float* ewv = (const float*)d_in[16], *ebp = (const float*)d_in[17];
    const float* cp  = (const float*)d_in[18];
    const float* gh  = (const float*)d_in[19], *bh = (const float*)d_in[20];
    const float* ge  = (const float*)d_in[21], *be = (const float*)d_in[22];

    float* out_h = (float*)d_out;
    float* out_e = out_h + (size_t)BV * Hn;                 // +131072
    float* out_x = out_e + (size_t)NE * Hn;                 // +33554432

    const int smem_bytes = 25664 * 4;   // 102656
    cudaFuncSetAttribute(k_main, cudaFuncAttributeMaxDynamicSharedMemorySize, smem_bytes);

    k_node_lin<<<64, 256>>>(h, Uw, Ub, Vw, Vb, Aw, Ab, Bw, Bb);
    k_main<<<K1_BLOCKS, 256, smem_bytes>>>(e, x, graph, Cw, Cb, dwv, dbv, ewv, ebp, cp,
                                           out_e, out_x);
    k_stats<<<1, 128>>>(gh, bh, ge, be);
    k_h_out<<<512, 256>>>(h, out_h);
    k_e_out<<<32768, 256>>>((const float4*)e, (float4*)out_e);
}

// round 3
// speedup vs baseline: 1.2969x; 1.2969x over previous
#include <cuda_runtime.h>
#include <cstdint>

// Problem constants
#define Hn 128
#define Vn 256
#define BV 1024            // B*V node count
#define NE 262144          // B*V*V edge count
#define NCTA 2048          // k_main CTAs: (b*V+i) * 2 j-halves

// ------------------------- device scratch --------------------------------
__device__ float g_Uh[BV * Hn];
__device__ float g_Vh[BV * Hn];
__device__ float g_Ah[BV * Hn];
__device__ float g_Bh[BV * Hn];
__device__ float g_hpre[BV * Hn];
__device__ float g_hpp[NCTA * Hn];     // per-CTA masked-aggregation partial
__device__ float g_ps[NCTA * Hn];      // per-CTA per-channel sum of e_new
__device__ float g_ps2[NCTA * Hn];
__device__ float g_xp[NCTA * 2];       // per-CTA partial x update
__device__ float g_rs_e[Hn], g_ofs_e[Hn];
__device__ float g_rs_h[Hn], g_ofs_h[Hn];

__device__ __forceinline__ float sigmoidf_(float v) {
    return 1.0f / (1.0f + __expf(-v));
}

__device__ __forceinline__ uint32_t smem_u32(const void* p) {
    uint32_t a;
    asm("{ .reg .u64 t; cvta.to.shared.u64 t, %1; cvt.u32.u64 %0, t; }"
        : "=r"(a) : "l"(p));
    return a;
}

// pack two fp32 -> bf16x2 (lo lane = a, hi lane = b)
__device__ __forceinline__ uint32_t pack_bf16(float a, float b) {
    uint32_t r;
    asm("cvt.rn.bf16x2.f32 %0, %1, %2;" : "=r"(r) : "f"(b), "f"(a));
    return r;
}

__device__ __forceinline__ void ldsm_x4(uint32_t& r0, uint32_t& r1, uint32_t& r2,
                                        uint32_t& r3, uint32_t addr) {
    asm volatile("ldmatrix.sync.aligned.m8n8.x4.shared.b16 {%0,%1,%2,%3}, [%4];"
                 : "=r"(r0), "=r"(r1), "=r"(r2), "=r"(r3) : "r"(addr));
}

__device__ __forceinline__ void ldsm_x2(uint32_t& r0, uint32_t& r1, uint32_t addr) {
    asm volatile("ldmatrix.sync.aligned.m8n8.x2.shared.b16 {%0,%1}, [%2];"
                 : "=r"(r0), "=r"(r1) : "r"(addr));
}

__device__ __forceinline__ void mma16816(float* d, const uint32_t* a, const uint32_t* b) {
    asm volatile(
        "mma.sync.aligned.m16n8k16.row.col.f32.bf16.bf16.f32 "
        "{%0,%1,%2,%3}, {%4,%5,%6,%7}, {%8,%9}, {%0,%1,%2,%3};"
        : "+f"(d[0]), "+f"(d[1]), "+f"(d[2]), "+f"(d[3])
        : "r"(a[0]), "r"(a[1]), "r"(a[2]), "r"(a[3]), "r"(b[0]), "r"(b[1]));
}

// ------------------------- K0: node linears Uh/Vh/Ah/Bh -------------------
__global__ void k_node_lin(const float* __restrict__ h,
                           const float* __restrict__ Uw, const float* __restrict__ Ub,
                           const float* __restrict__ Vw, const float* __restrict__ Vb,
                           const float* __restrict__ Aw, const float* __restrict__ Ab,
                           const float* __restrict__ Bw, const float* __restrict__ Bb) {
    __shared__ float hs[16 * Hn];
    int tid = threadIdx.x;
    int row0 = blockIdx.x * 16;
    for (int idx = tid; idx < 16 * Hn; idx += 256)
        hs[idx] = h[(size_t)row0 * Hn + idx];
    __syncthreads();
    const float* Ws[4] = {Uw, Vw, Aw, Bw};
    const float* bs[4] = {Ub, Vb, Ab, Bb};
    float* outs[4];
    outs[0] = g_Uh; outs[1] = g_Vh; outs[2] = g_Ah; outs[3] = g_Bh;
    for (int p = 0; p < 2; p++) {
        int cid = tid + 256 * p;
        int m = cid >> 7;
        int o = cid & 127;
        const float* W = Ws[m] + (size_t)o * Hn;
        float acc[16];
        #pragma unroll
        for (int r = 0; r < 16; r++) acc[r] = 0.f;
        for (int k = 0; k < Hn; k += 4) {
            float4 w = *(const float4*)(W + k);
            #pragma unroll
            for (int r = 0; r < 16; r++) {
                acc[r] += hs[r * Hn + k] * w.x + hs[r * Hn + k + 1] * w.y +
                          hs[r * Hn + k + 2] * w.z + hs[r * Hn + k + 3] * w.w;
            }
        }
        float bias = bs[m][o];
        float* op = outs[m] + (size_t)row0 * Hn + o;
        #pragma unroll
        for (int r = 0; r < 16; r++) op[(size_t)r * Hn] = acc[r] + bias;
    }
}

// ------------------------- K1: split-bf16 mma.sync main kernel ------------
// SMEM byte layout (dynamic):
static constexpr int SA_HI = 0;        // 32768 : A hi bf16 (128x128, swizzled)
static constexpr int SA_LO = 32768;    // 32768
static constexpr int SB_HI = 65536;    // 32768 : B = Cw
static constexpr int SB_LO = 98304;    // 32768
// reuse after MMA:
static constexpr int STAGE  = 0;       // 128 rows x 132 floats = 67584 B
static constexpr int RED_PS  = 98304;  // 8x128 floats
static constexpr int RED_PS2 = 102400;
static constexpr int RED_M   = 106496; // end 110592 (inside dead B_lo)
// persistent misc:
static constexpr int SM_BC   = 131072; // 128 f : Bh_i + Cb + db
static constexpr int SM_DW   = 131584;
static constexpr int SM_EW   = 132096;
static constexpr int SM_DIST = 132608;
static constexpr int SM_DFX  = 133120;
static constexpr int SM_DFY  = 133632;
static constexpr int SM_SPA  = 134144;
static constexpr int SM_GR   = 134656; // 128 ints
static constexpr int SM_RED  = 135168; // 16 f
static constexpr int SMEM_MAIN = 135296;

// convert 128x128 fp32 (row-major) -> split-bf16 hi/lo, 16B-chunk XOR swizzle
__device__ __forceinline__ void cvt_store_tile(const float4* __restrict__ src,
                                               char* dst_hi, char* dst_lo, int tid) {
    #pragma unroll
    for (int q = 0; q < 16; q++) {
        int idx = tid + 256 * q;          // float4 index 0..4095
        float4 v = __ldg(src + idx);
        int row = idx >> 5;
        int c4f = idx & 31;               // float4-within-row
        uint32_t h0 = pack_bf16(v.x, v.y);
        uint32_t h1 = pack_bf16(v.z, v.w);
        float r0 = v.x - __uint_as_float(h0 << 16);
        float r1 = v.y - __uint_as_float(h0 & 0xffff0000u);
        float r2 = v.z - __uint_as_float(h1 << 16);
        float r3 = v.w - __uint_as_float(h1 & 0xffff0000u);
        uint32_t l0 = pack_bf16(r0, r1);
        uint32_t l1 = pack_bf16(r2, r3);
        int off = row * 256 + (((c4f >> 1) ^ (row & 7)) << 4) + ((c4f & 1) << 3);
        *(uint2*)(dst_hi + off) = make_uint2(h0, h1);
        *(uint2*)(dst_lo + off) = make_uint2(l0, l1);
    }
}

__global__ void __launch_bounds__(256, 1)
k_main(const float* __restrict__ e, const float* __restrict__ x,
       const int* __restrict__ graph,
       const float* __restrict__ Cw, const float* __restrict__ Cb,
       const float* __restrict__ dwv, const float* __restrict__ dbv,
       const float* __restrict__ ewv, const float* __restrict__ ebp,
       float* __restrict__ out_e) {
    extern __shared__ char sm[];
    uint32_t smb = smem_u32(sm);
    int tid = threadIdx.x;
    int wid = tid >> 5;
    int lane = tid & 31;

    int i_glob = blockIdx.x >> 1;     // b*V + i
    int half = blockIdx.x & 1;
    int b = i_glob >> 8;
    int jbase = half * 128;

    float* sBC   = (float*)(sm + SM_BC);
    float* sdw   = (float*)(sm + SM_DW);
    float* sew   = (float*)(sm + SM_EW);
    float* sdist = (float*)(sm + SM_DIST);
    float* sdfx  = (float*)(sm + SM_DFX);
    float* sdfy  = (float*)(sm + SM_DFY);
    float* spa   = (float*)(sm + SM_SPA);
    int*   sgr   = (int*)(sm + SM_GR);
    float* sred  = (float*)(sm + SM_RED);

    float xi = x[i_glob * 2], yi = x[i_glob * 2 + 1];
    if (tid < 128) {
        sBC[tid] = g_Bh[(size_t)i_glob * Hn + tid] + Cb[tid] + dbv[tid];
        sdw[tid] = dwv[tid];
        sew[tid] = ewv[tid];
        int jg = jbase + tid;
        float dx = xi - x[(b * Vn + jg) * 2];
        float dy = yi - x[(b * Vn + jg) * 2 + 1];
        float d2 = dx * dx + dy * dy;
        sdist[tid] = d2 > 0.f ? sqrtf(d2) : 0.f;
        sdfx[tid] = dx; sdfy[tid] = dy;
        sgr[tid] = graph[(size_t)i_glob * Vn + jg];
    }

    cvt_store_tile((const float4*)(e + ((size_t)i_glob * Vn + jbase) * Hn),
                   sm + SA_HI, sm + SA_LO, tid);
    cvt_store_tile((const float4*)Cw, sm + SB_HI, sm + SB_LO, tid);
    __syncthreads();

    // ---- MMA phase: warp grid 2(m) x 4(n); warp tile 64x32 ----
    int wm = wid & 1;
    int wn = wid >> 1;

    float acc[4][4][4];
    #pragma unroll
    for (int mi = 0; mi < 4; mi++)
        #pragma unroll
        for (int ni = 0; ni < 4; ni++)
            #pragma unroll
            for (int c = 0; c < 4; c++) acc[mi][ni][c] = 0.f;

    // per-lane row components
    int la7 = lane & 7;
    int rowA_base = wm * 64 + la7 + ((lane >> 3) & 1) * 8;   // + mi*16
    int a_chunk_lane = lane >> 4;                            // 0/1
    int lane2 = lane & 15;
    int rowB_base = wn * 32 + (lane2 & 7);                   // + ni*8
    int b_chunk_lane = lane2 >> 3;                           // 0/1

    #pragma unroll
    for (int pass = 0; pass < 3; pass++) {
        uint32_t abase = smb + (pass == 1 ? SA_LO : SA_HI);
        uint32_t bbase = smb + (pass == 2 ? SB_LO : SB_HI);
        #pragma unroll
        for (int ks = 0; ks < 8; ks++) {
            uint32_t af[4][4];
            #pragma unroll
            for (int mi = 0; mi < 4; mi++) {
                int r = rowA_base + mi * 16;
                uint32_t addr = abase + r * 256 +
                                (((ks * 2 + a_chunk_lane) ^ (r & 7)) << 4);
                ldsm_x4(af[mi][0], af[mi][1], af[mi][2], af[mi][3], addr);
            }
            uint32_t bf[4][2];
            #pragma unroll
            for (int ni = 0; ni < 4; ni++) {
                int r = rowB_base + ni * 8;
                uint32_t addr = bbase + r * 256 +
                                (((ks * 2 + b_chunk_lane) ^ (r & 7)) << 4);
                ldsm_x2(bf[ni][0], bf[ni][1], addr);
            }
            #pragma unroll
            for (int mi = 0; mi < 4; mi++)
                #pragma unroll
                for (int ni = 0; ni < 4; ni++)
                    mma16816(acc[mi][ni], af[mi], bf[ni]);
        }
    }
    __syncthreads();

    // ---- stage accumulators to padded fp32 SMEM (row stride 132 floats) ----
    float* stage = (float*)(sm + STAGE);
    {
        int r0 = wm * 64 + (lane >> 2);
        int c0 = wn * 32 + (lane & 3) * 2;
        #pragma unroll
        for (int mi = 0; mi < 4; mi++)
            #pragma unroll
            for (int ni = 0; ni < 4; ni++) {
                int r = r0 + mi * 16;
                int c = c0 + ni * 8;
                *(float2*)(stage + r * 132 + c) =
                    make_float2(acc[mi][ni][0], acc[mi][ni][1]);
                *(float2*)(stage + (r + 8) * 132 + c) =
                    make_float2(acc[mi][ni][2], acc[mi][ni][3]);
            }
    }
    __syncthreads();

    // ---- fused coalesced epilogue ----
    int c4 = tid & 31;
    int col = c4 * 4;
    float bc0 = sBC[col], bc1 = sBC[col + 1], bc2 = sBC[col + 2], bc3 = sBC[col + 3];
    float dw0 = sdw[col], dw1 = sdw[col + 1], dw2 = sdw[col + 2], dw3 = sdw[col + 3];
    float ew0 = sew[col], ew1 = sew[col + 1], ew2 = sew[col + 2], ew3 = sew[col + 3];
    float ps0 = 0.f, ps1 = 0.f, ps2_ = 0.f, ps3 = 0.f;
    float q0 = 0.f, q1 = 0.f, q2 = 0.f, q3 = 0.f;
    float m0 = 0.f, m1 = 0.f, m2 = 0.f, m3 = 0.f;

    float* dst = out_e + ((size_t)i_glob * Vn + jbase) * Hn;

    #pragma unroll
    for (int q = 0; q < 16; q++) {
        int row = (tid >> 5) + 8 * q;       // same row across the whole warp
        float4 t4 = *(float4*)(stage + row * 132 + col);
        size_t nrow = ((size_t)(b * Vn + jbase + row)) * Hn + col;
        float4 a = __ldg((const float4*)(g_Ah + nrow));
        float4 vh = __ldg((const float4*)(g_Vh + nrow));
        float dist = sdist[row];
        float t0 = t4.x + a.x + bc0 + dist * dw0;
        float t1 = t4.y + a.y + bc1 + dist * dw1;
        float t2 = t4.z + a.z + bc2 + dist * dw2;
        float t3 = t4.w + a.w + bc3 + dist * dw3;
        *(float4*)(dst + (size_t)row * Hn + col) = make_float4(t0, t1, t2, t3);
        ps0 += t0; ps1 += t1; ps2_ += t2; ps3 += t3;
        q0 += t0 * t0; q1 += t1 * t1; q2 += t2 * t2; q3 += t3 * t3;
        if (sgr[row] != 1) {
            m0 += sigmoidf_(t0) * vh.x;
            m1 += sigmoidf_(t1) * vh.y;
            m2 += sigmoidf_(t2) * vh.z;
            m3 += sigmoidf_(t3) * vh.w;
        }
        float pd = t0 * ew0 + t1 * ew1 + t2 * ew2 + t3 * ew3;
        #pragma unroll
        for (int o = 16; o > 0; o >>= 1) pd += __shfl_xor_sync(0xffffffffu, pd, o);
        if (lane == 0) spa[row] = pd;
    }

    ((float4*)(sm + RED_PS))[wid * 32 + c4]  = make_float4(ps0, ps1, ps2_, ps3);
    ((float4*)(sm + RED_PS2))[wid * 32 + c4] = make_float4(q0, q1, q2, q3);
    ((float4*)(sm + RED_M))[wid * 32 + c4]   = make_float4(m0, m1, m2, m3);
    __syncthreads();

    if (tid < 128) {
        float s = 0.f, s2 = 0.f, mm = 0.f;
        const float* rp = (const float*)(sm + RED_PS);
        const float* rq = (const float*)(sm + RED_PS2);
        const float* rm = (const float*)(sm + RED_M);
        #pragma unroll
        for (int w = 0; w < 8; w++) {
            s  += rp[w * 128 + tid];
            s2 += rq[w * 128 + tid];
            mm += rm[w * 128 + tid];
        }
        g_ps[(size_t)blockIdx.x * Hn + tid]  = s;
        g_ps2[(size_t)blockIdx.x * Hn + tid] = s2;
        g_hpp[(size_t)blockIdx.x * Hn + tid] = mm;

        float pa = sigmoidf_(spa[tid] + ebp[0]);
        float px = pa * sdfx[tid];
        float py = pa * sdfy[tid];
        #pragma unroll
        for (int o = 16; o > 0; o >>= 1) {
            px += __shfl_xor_sync(0xffffffffu, px, o);
            py += __shfl_xor_sync(0xffffffffu, py, o);
        }
        if (lane == 0) { sred[wid] = px; sred[8 + wid] = py; }
    }
    __syncthreads();
    if (tid == 0) {
        float sx = sred[0] + sred[1] + sred[2] + sred[3];
        float sy = sred[8] + sred[9] + sred[10] + sred[11];
        g_xp[blockIdx.x * 2] = sx;
        g_xp[blockIdx.x * 2 + 1] = sy;
    }
}

// ------------------------- K2: BN statistics ------------------------------
__global__ void k_stats(const float* __restrict__ gamma_h, const float* __restrict__ beta_h,
                        const float* __restrict__ gamma_e, const float* __restrict__ beta_e) {
    __shared__ double sd[8][Hn][2];
    int tid = threadIdx.x;      // 1024 threads
    int ch = tid & 127;
    int part = tid >> 7;        // 0..7

    double s = 0.0, s2 = 0.0;
    for (int p = part * 256; p < part * 256 + 256; p++) {
        s  += (double)g_ps[(size_t)p * Hn + ch];
        s2 += (double)g_ps2[(size_t)p * Hn + ch];
    }
    sd[part][ch][0] = s; sd[part][ch][1] = s2;
    __syncthreads();
    if (part == 0) {
        for (int r = 1; r < 8; r++) { s += sd[r][ch][0]; s2 += sd[r][ch][1]; }
        float mu  = (float)(s  / (double)NE);
        float var = (float)(s2 / (double)NE) - mu * mu;
        float rs = gamma_e[ch] * rsqrtf(var + 1e-5f);
        g_rs_e[ch] = rs;
        g_ofs_e[ch] = beta_e[ch] - mu * rs;
    }
    __syncthreads();

    s = 0.0; s2 = 0.0;
    for (int r = part * 128; r < part * 128 + 128; r++) {
        float v = g_Uh[(size_t)r * Hn + ch] +
                  g_hpp[(size_t)(2 * r) * Hn + ch] +
                  g_hpp[(size_t)(2 * r + 1) * Hn + ch];
        g_hpre[(size_t)r * Hn + ch] = v;
        s += (double)v; s2 += (double)v * (double)v;
    }
    sd[part][ch][0] = s; sd[part][ch][1] = s2;
    __syncthreads();
    if (part == 0) {
        for (int r = 1; r < 8; r++) { s += sd[r][ch][0]; s2 += sd[r][ch][1]; }
        float mu  = (float)(s  / (double)BV);
        float var = (float)(s2 / (double)BV) - mu * mu;
        float rs = gamma_h[ch] * rsqrtf(var + 1e-5f);
        g_rs_h[ch] = rs;
        g_ofs_h[ch] = beta_h[ch] - mu * rs;
    }
}

// ------------------------- K3h: h residual + BN + ReLU --------------------
__global__ void k_h_out(const float* __restrict__ h, float* __restrict__ out_h) {
    int idx = blockIdx.x * 256 + threadIdx.x;
    int ch = idx & 127;
    float v = fmaf(g_hpre[idx], g_rs_h[ch], g_ofs_h[ch]);
    out_h[idx] = h[idx] + fmaxf(v, 0.f);
}

// ------------------------- K3x: combine x partials ------------------------
__global__ void k_x_out(const float* __restrict__ x, const float* __restrict__ cp,
                        float* __restrict__ out_x) {
    int idx = blockIdx.x * 256 + threadIdx.x;   // 1024 nodes
    float c = cp[0];
    out_x[2 * idx]     = x[2 * idx]     + c * (g_xp[4 * idx + 0] + g_xp[4 * idx + 2]);
    out_x[2 * idx + 1] = x[2 * idx + 1] + c * (g_xp[4 * idx + 1] + g_xp[4 * idx + 3]);
}

// ------------------------- K3e: e residual + BN + ReLU (in place) ---------
__global__ void k_e_out(const float4* __restrict__ e, float4* __restrict__ oe) {
    int idx = blockIdx.x * 256 + threadIdx.x;   // 8388608 float4
    int c4 = idx & 31;
    float4 rs = *(const float4*)(g_rs_e + 4 * c4);
    float4 of = *(const float4*)(g_ofs_e + 4 * c4);
    float4 en = oe[idx];
    float4 ev = __ldg(e + idx);
    ev.x += fmaxf(fmaf(en.x, rs.x, of.x), 0.f);
    ev.y += fmaxf(fmaf(en.y, rs.y, of.y), 0.f);
    ev.z += fmaxf(fmaf(en.z, rs.z, of.z), 0.f);
    ev.w += fmaxf(fmaf(en.w, rs.w, of.w), 0.f);
    oe[idx] = ev;
}

// ------------------------- launcher ---------------------------------------
extern "C" void kernel_launch(void* const* d_in, const int* in_sizes, int n_in,
                              void* d_out, int out_size) {
    const float* h     = (const float*)d_in[0];
    const float* e     = (const float*)d_in[1];
    const float* x     = (const float*)d_in[2];
    const int*   graph = (const int*)d_in[3];
    const float* Uw = (const float*)d_in[4],  *Ub = (const float*)d_in[5];
    const float* Vw = (const float*)d_in[6],  *Vb = (const float*)d_in[7];
    const float* Aw = (const float*)d_in[8],  *Ab = (const float*)d_in[9];
    const float* Bw = (const float*)d_in[10], *Bb = (const float*)d_in[11];
    const float* Cw = (const float*)d_in[12], *Cb = (const float*)d_in[13];
    const float* dwv = (const float*)d_in[14], *dbv = (const float*)d_in[15];
    const float* ewv = (const float*)d_in[16], *ebp = (const float*)d_in[17];
    const float* cp  = (const float*)d_in[18];
    const float* gh  = (const float*)d_in[19], *bh = (const float*)d_in[20];
    const float* ge  = (const float*)d_in[21], *be = (const float*)d_in[22];

    float* out_h = (float*)d_out;
    float* out_e = out_h + (size_t)BV * Hn;
    float* out_x = out_e + (size_t)NE * Hn;

    cudaFuncSetAttribute(k_main, cudaFuncAttributeMaxDynamicSharedMemorySize, SMEM_MAIN);

    k_node_lin<<<64, 256>>>(h, Uw, Ub, Vw, Vb, Aw, Ab, Bw, Bb);
    k_main<<<NCTA, 256, SMEM_MAIN>>>(e, x, graph, Cw, Cb, dwv, dbv, ewv, ebp, out_e);
    k_stats<<<1, 1024>>>(gh, bh, ge, be);
    k_h_out<<<512, 256>>>(h, out_h);
    k_x_out<<<4, 256>>>(x, cp, out_x);
    k_e_out<<<32768, 256>>>((const float4*)e, (float4*)out_e);
}

// round 4
// speedup vs baseline: 2.7490x; 2.1196x over previous
#include <cuda_runtime.h>
#include <cstdint>

// Problem constants
#define Hn 128
#define Vn 256
#define BV 1024            // B*V node count
#define NE 262144          // B*V*V edge count

// ------------------------- device scratch --------------------------------
__device__ float g_Uh[BV * Hn];
__device__ float g_Vh[BV * Hn];
__device__ float g_Ah[BV * Hn];
__device__ float g_Bh[BV * Hn];
__device__ float g_hpre[BV * Hn];
__device__ float g_hpp[2048 * Hn];     // per-(i,jh) masked-aggregation partial
__device__ float g_ps[2048 * Hn];      // per-(i,jh) per-channel sum of e_new
__device__ float g_ps2[2048 * Hn];
__device__ float g_pd0[NE];            // pa-dot partial, n-half 0
__device__ float g_pd1[NE];            // pa-dot partial, n-half 1
__device__ float g_pse[64 * Hn], g_pse2[64 * Hn];   // stats partials
__device__ float g_psh[64 * Hn], g_psh2[64 * Hn];
__device__ float g_rs_e[Hn], g_ofs_e[Hn];
__device__ float g_rs_h[Hn], g_ofs_h[Hn];
__device__ uint8_t g_CwHi[32768];      // pre-swizzled split-bf16 Cw
__device__ uint8_t g_CwLo[32768];

__device__ __forceinline__ float sigmoidf_(float v) {
    return 1.0f / (1.0f + __expf(-v));
}

__device__ __forceinline__ uint32_t smem_u32(const void* p) {
    uint32_t a;
    asm("{ .reg .u64 t; cvta.to.shared.u64 t, %1; cvt.u32.u64 %0, t; }"
        : "=r"(a) : "l"(p));
    return a;
}

// pack two fp32 -> bf16x2 (lo lane = a, hi lane = b)
__device__ __forceinline__ uint32_t pack_bf16(float a, float b) {
    uint32_t r;
    asm("cvt.rn.bf16x2.f32 %0, %1, %2;" : "=r"(r) : "f"(b), "f"(a));
    return r;
}

__device__ __forceinline__ void ldsm_x4(uint32_t& r0, uint32_t& r1, uint32_t& r2,
                                        uint32_t& r3, uint32_t addr) {
    asm volatile("ldmatrix.sync.aligned.m8n8.x4.shared.b16 {%0,%1,%2,%3}, [%4];"
                 : "=r"(r0), "=r"(r1), "=r"(r2), "=r"(r3) : "r"(addr));
}

__device__ __forceinline__ void ldsm_x2(uint32_t& r0, uint32_t& r1, uint32_t addr) {
    asm volatile("ldmatrix.sync.aligned.m8n8.x2.shared.b16 {%0,%1}, [%2];"
                 : "=r"(r0), "=r"(r1) : "r"(addr));
}

__device__ __forceinline__ void mma16816(float* d, const uint32_t* a, const uint32_t* b) {
    asm volatile(
        "mma.sync.aligned.m16n8k16.row.col.f32.bf16.bf16.f32 "
        "{%0,%1,%2,%3}, {%4,%5,%6,%7}, {%8,%9}, {%0,%1,%2,%3};"
        : "+f"(d[0]), "+f"(d[1]), "+f"(d[2]), "+f"(d[3])
        : "r"(a[0]), "r"(a[1]), "r"(a[2]), "r"(a[3]), "r"(b[0]), "r"(b[1]));
}

// split one float4 into hi/lo bf16x2 pairs
__device__ __forceinline__ void split4(float4 v, uint2& hi, uint2& lo) {
    uint32_t h0 = pack_bf16(v.x, v.y);
    uint32_t h1 = pack_bf16(v.z, v.w);
    float r0 = v.x - __uint_as_float(h0 << 16);
    float r1 = v.y - __uint_as_float(h0 & 0xffff0000u);
    float r2 = v.z - __uint_as_float(h1 << 16);
    float r3 = v.w - __uint_as_float(h1 & 0xffff0000u);
    hi = make_uint2(h0, h1);
    lo = make_uint2(pack_bf16(r0, r1), pack_bf16(r2, r3));
}

__device__ __forceinline__ int sw_off(int idx /*float4 index*/) {
    int row = idx >> 5;
    int c4f = idx & 31;
    return row * 256 + (((c4f >> 1) ^ (row & 7)) << 4) + ((c4f & 1) << 3);
}

// ------------------------- K-1: pre-convert Cw ----------------------------
__global__ void k_prep(const float* __restrict__ Cw) {
    int idx = blockIdx.x * 256 + threadIdx.x;   // 4096 float4s
    float4 v = __ldg((const float4*)Cw + idx);
    uint2 hi, lo;
    split4(v, hi, lo);
    int off = sw_off(idx);
    *(uint2*)(g_CwHi + off) = hi;
    *(uint2*)(g_CwLo + off) = lo;
}

// ------------------------- K0: node linears Uh/Vh/Ah/Bh -------------------
__global__ void k_node_lin(const float* __restrict__ h,
                           const float* __restrict__ Uw, const float* __restrict__ Ub,
                           const float* __restrict__ Vw, const float* __restrict__ Vb,
                           const float* __restrict__ Aw, const float* __restrict__ Ab,
                           const float* __restrict__ Bw, const float* __restrict__ Bb) {
    __shared__ float hs[16 * Hn];
    int tid = threadIdx.x;
    int row0 = blockIdx.x * 16;
    for (int idx = tid; idx < 16 * Hn; idx += 256)
        hs[idx] = h[(size_t)row0 * Hn + idx];
    __syncthreads();
    const float* Ws[4] = {Uw, Vw, Aw, Bw};
    const float* bs[4] = {Ub, Vb, Ab, Bb};
    float* outs[4];
    outs[0] = g_Uh; outs[1] = g_Vh; outs[2] = g_Ah; outs[3] = g_Bh;
    for (int p = 0; p < 2; p++) {
        int cid = tid + 256 * p;
        int m = cid >> 7;
        int o = cid & 127;
        const float* W = Ws[m] + (size_t)o * Hn;
        float acc[16];
        #pragma unroll
        for (int r = 0; r < 16; r++) acc[r] = 0.f;
        for (int k = 0; k < Hn; k += 4) {
            float4 w = *(const float4*)(W + k);
            #pragma unroll
            for (int r = 0; r < 16; r++) {
                acc[r] += hs[r * Hn + k] * w.x + hs[r * Hn + k + 1] * w.y +
                          hs[r * Hn + k + 2] * w.z + hs[r * Hn + k + 3] * w.w;
            }
        }
        float bias = bs[m][o];
        float* op = outs[m] + (size_t)row0 * Hn + o;
        #pragma unroll
        for (int r = 0; r < 16; r++) op[(size_t)r * Hn] = acc[r] + bias;
    }
}

// ------------------------- K1: main kernel (128j x 64n tile) --------------
// grid 4096: blockIdx = ((i_glob*2 + jh)*2 + nh)
static constexpr int SA_HI = 0;        // 32768
static constexpr int SA_LO = 32768;    // 32768
static constexpr int SB_HI = 65536;    // 16384
static constexpr int SB_LO = 81920;    // 16384
static constexpr int SM_BC   = 98304;  // 128 f
static constexpr int SM_DW   = 98816;
static constexpr int SM_EW   = 99328;
static constexpr int SM_DIST = 99840;
static constexpr int SM_GR   = 100352;
static constexpr int SM_SPA  = 100864; // 4 x 128 f
static constexpr int SM_RPS  = 102912; // 2 x 64 f
static constexpr int SM_RPS2 = 103424;
static constexpr int SM_RM   = 103936;
static constexpr int SMEM_MAIN = 104448;

__global__ void __launch_bounds__(256, 2)
k_main(const float* __restrict__ e, const float* __restrict__ x,
       const int* __restrict__ graph, const float* __restrict__ Cb,
       const float* __restrict__ dwv, const float* __restrict__ dbv,
       const float* __restrict__ ewv,
       float* __restrict__ out_e) {
    extern __shared__ char sm[];
    uint32_t smb = smem_u32(sm);
    int tid = threadIdx.x;
    int wid = tid >> 5;
    int lane = tid & 31;

    int bx = blockIdx.x;
    int i_glob = bx >> 2;          // b*V + i
    int jh = (bx >> 1) & 1;
    int nh = bx & 1;
    int b = i_glob >> 8;
    int jbase = jh * 128;

    float* sBC   = (float*)(sm + SM_BC);
    float* sdw   = (float*)(sm + SM_DW);
    float* sew   = (float*)(sm + SM_EW);
    float* sdist = (float*)(sm + SM_DIST);
    int*   sgr   = (int*)(sm + SM_GR);
    float* spa4  = (float*)(sm + SM_SPA);
    float* rps   = (float*)(sm + SM_RPS);
    float* rps2  = (float*)(sm + SM_RPS2);
    float* rmm   = (float*)(sm + SM_RM);

    float xi = x[i_glob * 2], yi = x[i_glob * 2 + 1];
    if (tid < 128) {
        sBC[tid] = g_Bh[(size_t)i_glob * Hn + tid] + Cb[tid] + dbv[tid];
        sdw[tid] = dwv[tid];
        sew[tid] = ewv[tid];
        int jg = jbase + tid;
        float dx = xi - x[(b * Vn + jg) * 2];
        float dy = yi - x[(b * Vn + jg) * 2 + 1];
        float d2 = dx * dx + dy * dy;
        sdist[tid] = d2 > 0.f ? sqrtf(d2) : 0.f;
        sgr[tid] = graph[(size_t)i_glob * Vn + jg];
    }

    // A: load + split-convert e tile (128x128)
    {
        const float4* src = (const float4*)(e + ((size_t)i_glob * Vn + jbase) * Hn);
        #pragma unroll
        for (int q = 0; q < 16; q++) {
            int idx = tid + 256 * q;
            float4 v = __ldg(src + idx);
            uint2 hi, lo;
            split4(v, hi, lo);
            int off = sw_off(idx);
            *(uint2*)(sm + SA_HI + off) = hi;
            *(uint2*)(sm + SA_LO + off) = lo;
        }
    }
    // B: straight copy of pre-converted Cw rows [nh*64, nh*64+64)
    {
        const uint4* srcH = (const uint4*)(g_CwHi) + nh * 1024;
        const uint4* srcL = (const uint4*)(g_CwLo) + nh * 1024;
        uint4* dstH = (uint4*)(sm + SB_HI);
        uint4* dstL = (uint4*)(sm + SB_LO);
        #pragma unroll
        for (int t = tid; t < 1024; t += 256) {
            dstH[t] = __ldg(srcH + t);
            dstL[t] = __ldg(srcL + t);
        }
    }
    __syncthreads();

    // ---- MMA: warp grid 2(m) x 4(n); warp tile 64x16 ----
    int wm = wid & 1;
    int wn = wid >> 1;

    float acc[4][2][4];
    #pragma unroll
    for (int mi = 0; mi < 4; mi++)
        #pragma unroll
        for (int ni = 0; ni < 2; ni++)
            #pragma unroll
            for (int c = 0; c < 4; c++) acc[mi][ni][c] = 0.f;

    int la7 = lane & 7;
    int rowA_base = wm * 64 + la7 + ((lane >> 3) & 1) * 8;
    int a_ch = lane >> 4;
    int lane2 = lane & 15;
    int rowB_off = lane2 & 7;
    int b_ch = lane2 >> 3;

    #pragma unroll
    for (int ks = 0; ks < 8; ks++) {
        uint32_t ah[4][4], al[4][4];
        #pragma unroll
        for (int mi = 0; mi < 4; mi++) {
            int r = rowA_base + mi * 16;
            uint32_t off = r * 256 + (((ks * 2 + a_ch) ^ (r & 7)) << 4);
            ldsm_x4(ah[mi][0], ah[mi][1], ah[mi][2], ah[mi][3], smb + SA_HI + off);
            ldsm_x4(al[mi][0], al[mi][1], al[mi][2], al[mi][3], smb + SA_LO + off);
        }
        uint32_t bh[2][2], bl[2][2];
        #pragma unroll
        for (int ni = 0; ni < 2; ni++) {
            int r = wn * 16 + ni * 8 + rowB_off;
            uint32_t off = r * 256 + (((ks * 2 + b_ch) ^ (r & 7)) << 4);
            ldsm_x2(bh[ni][0], bh[ni][1], smb + SB_HI + off);
            ldsm_x2(bl[ni][0], bl[ni][1], smb + SB_LO + off);
        }
        #pragma unroll
        for (int mi = 0; mi < 4; mi++)
            #pragma unroll
            for (int ni = 0; ni < 2; ni++) {
                mma16816(acc[mi][ni], ah[mi], bh[ni]);
                mma16816(acc[mi][ni], al[mi], bh[ni]);
                mma16816(acc[mi][ni], ah[mi], bl[ni]);
            }
    }

    // ---- epilogue straight from accumulators ----
    // thread element (mi, ni, rh, k): row = wm*64+mi*16+(lane>>2)+rh*8,
    //                                 col_local = wn*16+ni*8+(lane&3)*2+k
    int cl0 = wn * 16 + (lane & 3) * 2;            // + ni*8
    int cg0 = nh * 64 + cl0;
    float bcv[2][2], dwv_[2][2], ewv_[2][2];
    #pragma unroll
    for (int ni = 0; ni < 2; ni++) {
        bcv[ni][0] = sBC[cg0 + ni * 8];     bcv[ni][1] = sBC[cg0 + ni * 8 + 1];
        dwv_[ni][0] = sdw[cg0 + ni * 8];    dwv_[ni][1] = sdw[cg0 + ni * 8 + 1];
        ewv_[ni][0] = sew[cg0 + ni * 8];    ewv_[ni][1] = sew[cg0 + ni * 8 + 1];
    }
    float cs[2][2], cs2[2][2], cm[2][2];
    #pragma unroll
    for (int ni = 0; ni < 2; ni++)
        #pragma unroll
        for (int k = 0; k < 2; k++) { cs[ni][k] = 0.f; cs2[ni][k] = 0.f; cm[ni][k] = 0.f; }

    float* dste = out_e + ((size_t)i_glob * Vn + jbase) * Hn;

    #pragma unroll
    for (int mi = 0; mi < 4; mi++) {
        #pragma unroll
        for (int rh = 0; rh < 2; rh++) {
            int r = wm * 64 + mi * 16 + (lane >> 2) + rh * 8;
            float dist = sdist[r];
            bool keep = (sgr[r] != 1);
            size_t nrow = ((size_t)(b * Vn + jbase + r)) * Hn;
            float pd = 0.f;
            #pragma unroll
            for (int ni = 0; ni < 2; ni++) {
                int cg = cg0 + ni * 8;
                float2 a = *(const float2*)(g_Ah + nrow + cg);
                float2 vh = *(const float2*)(g_Vh + nrow + cg);
                float t0 = acc[mi][ni][rh * 2 + 0] + a.x + bcv[ni][0] + dist * dwv_[ni][0];
                float t1 = acc[mi][ni][rh * 2 + 1] + a.y + bcv[ni][1] + dist * dwv_[ni][1];
                *(float2*)(dste + (size_t)r * Hn + cg) = make_float2(t0, t1);
                cs[ni][0] += t0; cs[ni][1] += t1;
                cs2[ni][0] += t0 * t0; cs2[ni][1] += t1 * t1;
                if (keep) {
                    cm[ni][0] += sigmoidf_(t0) * vh.x;
                    cm[ni][1] += sigmoidf_(t1) * vh.y;
                }
                pd += t0 * ewv_[ni][0] + t1 * ewv_[ni][1];
            }
            pd += __shfl_xor_sync(0xffffffffu, pd, 1);
            pd += __shfl_xor_sync(0xffffffffu, pd, 2);
            if ((lane & 3) == 0) spa4[wn * 128 + r] = pd;
        }
    }

    // column reductions across row-groups (8 lanes stride 4)
    #pragma unroll
    for (int ni = 0; ni < 2; ni++)
        #pragma unroll
        for (int k = 0; k < 2; k++) {
            #pragma unroll
            for (int o = 4; o < 32; o <<= 1) {
                cs[ni][k]  += __shfl_xor_sync(0xffffffffu, cs[ni][k], o);
                cs2[ni][k] += __shfl_xor_sync(0xffffffffu, cs2[ni][k], o);
                cm[ni][k]  += __shfl_xor_sync(0xffffffffu, cm[ni][k], o);
            }
        }
    if (lane < 4) {
        #pragma unroll
        for (int ni = 0; ni < 2; ni++) {
            int c = wn * 16 + ni * 8 + lane * 2;
            rps[wm * 64 + c]  = cs[ni][0];  rps[wm * 64 + c + 1]  = cs[ni][1];
            rps2[wm * 64 + c] = cs2[ni][0]; rps2[wm * 64 + c + 1] = cs2[ni][1];
            rmm[wm * 64 + c]  = cm[ni][0];  rmm[wm * 64 + c + 1]  = cm[ni][1];
        }
    }
    __syncthreads();

    if (tid < 64) {
        size_t gi = ((size_t)i_glob * 2 + jh) * Hn + nh * 64 + tid;
        g_ps[gi]  = rps[tid]  + rps[64 + tid];
        g_ps2[gi] = rps2[tid] + rps2[64 + tid];
        g_hpp[gi] = rmm[tid]  + rmm[64 + tid];
    }
    if (tid >= 128 && tid < 256) {
        int r = tid - 128;
        float pdt = spa4[r] + spa4[128 + r] + spa4[256 + r] + spa4[384 + r];
        float* gpd = nh ? g_pd1 : g_pd0;
        gpd[(size_t)i_glob * Vn + jbase + r] = pdt;
    }
}

// ------------------------- K2a: stats partials ----------------------------
__global__ void __launch_bounds__(128)
k_stats1() {
    int ch = threadIdx.x;
    int c = blockIdx.x;        // 64 blocks, 16 nodes each
    double se = 0.0, se2 = 0.0, sh = 0.0, sh2 = 0.0;
    for (int i = c * 16; i < c * 16 + 16; i++) {
        float hv = g_Uh[(size_t)i * Hn + ch] +
                   g_hpp[(size_t)(2 * i) * Hn + ch] +
                   g_hpp[(size_t)(2 * i + 1) * Hn + ch];
        g_hpre[(size_t)i * Hn + ch] = hv;
        sh += (double)hv; sh2 += (double)hv * (double)hv;
        se  += (double)g_ps[(size_t)(2 * i) * Hn + ch]  + (double)g_ps[(size_t)(2 * i + 1) * Hn + ch];
        se2 += (double)g_ps2[(size_t)(2 * i) * Hn + ch] + (double)g_ps2[(size_t)(2 * i + 1) * Hn + ch];
    }
    g_pse[c * Hn + ch]  = (float)se;
    g_pse2[c * Hn + ch] = (float)se2;
    g_psh[c * Hn + ch]  = (float)sh;
    g_psh2[c * Hn + ch] = (float)sh2;
}

// ------------------------- K2b: stats finalize ----------------------------
__global__ void __launch_bounds__(128)
k_stats2(const float* __restrict__ gamma_h, const float* __restrict__ beta_h,
         const float* __restrict__ gamma_e, const float* __restrict__ beta_e) {
    int ch = threadIdx.x;
    double se = 0.0, se2 = 0.0, sh = 0.0, sh2 = 0.0;
    for (int c = 0; c < 64; c++) {
        se  += (double)g_pse[c * Hn + ch];
        se2 += (double)g_pse2[c * Hn + ch];
        sh  += (double)g_psh[c * Hn + ch];
        sh2 += (double)g_psh2[c * Hn + ch];
    }
    float mu  = (float)(se / (double)NE);
    float var = (float)(se2 / (double)NE) - mu * mu;
    float rs = gamma_e[ch] * rsqrtf(var + 1e-5f);
    g_rs_e[ch] = rs;
    g_ofs_e[ch] = beta_e[ch] - mu * rs;

    float muh  = (float)(sh / (double)BV);
    float varh = (float)(sh2 / (double)BV) - muh * muh;
    float rsh = gamma_h[ch] * rsqrtf(varh + 1e-5f);
    g_rs_h[ch] = rsh;
    g_ofs_h[ch] = beta_h[ch] - muh * rsh;
}

// ------------------------- K3h: h residual + BN + ReLU --------------------
__global__ void k_h_out(const float* __restrict__ h, float* __restrict__ out_h) {
    int idx = blockIdx.x * 256 + threadIdx.x;
    int ch = idx & 127;
    float v = fmaf(g_hpre[idx], g_rs_h[ch], g_ofs_h[ch]);
    out_h[idx] = h[idx] + fmaxf(v, 0.f);
}

// ------------------------- K3x: finalize x --------------------------------
__global__ void __launch_bounds__(256)
k_x_out(const float* __restrict__ x, const float* __restrict__ cp,
        const float* __restrict__ ebp, float* __restrict__ out_x) {
    __shared__ float rx[8], ry[8];
    int i = blockIdx.x;            // node
    int j = threadIdx.x;
    int lane = j & 31, wid = j >> 5;
    int b = i >> 8;
    float xi = x[i * 2], yi = x[i * 2 + 1];
    float pd = g_pd0[(size_t)i * Vn + j] + g_pd1[(size_t)i * Vn + j];
    float pa = sigmoidf_(pd + ebp[0]);
    float dx = xi - x[(b * Vn + j) * 2];
    float dy = yi - x[(b * Vn + j) * 2 + 1];
    float px = pa * dx, py = pa * dy;
    #pragma unroll
    for (int o = 16; o > 0; o >>= 1) {
        px += __shfl_xor_sync(0xffffffffu, px, o);
        py += __shfl_xor_sync(0xffffffffu, py, o);
    }
    if (lane == 0) { rx[wid] = px; ry[wid] = py; }
    __syncthreads();
    if (j == 0) {
        float sx = 0.f, sy = 0.f;
        #pragma unroll
        for (int w = 0; w < 8; w++) { sx += rx[w]; sy += ry[w]; }
        float c = cp[0];
        out_x[i * 2]     = xi + c * sx;
        out_x[i * 2 + 1] = yi + c * sy;
    }
}

// ------------------------- K3e: e residual + BN + ReLU (in place) ---------
__global__ void k_e_out(const float4* __restrict__ e, float4* __restrict__ oe) {
    int idx = blockIdx.x * 256 + threadIdx.x;   // 8388608 float4
    int c4 = idx & 31;
    float4 rs = *(const float4*)(g_rs_e + 4 * c4);
    float4 of = *(const float4*)(g_ofs_e + 4 * c4);
    float4 en = oe[idx];
    float4 ev = __ldg(e + idx);
    ev.x += fmaxf(fmaf(en.x, rs.x, of.x), 0.f);
    ev.y += fmaxf(fmaf(en.y, rs.y, of.y), 0.f);
    ev.z += fmaxf(fmaf(en.z, rs.z, of.z), 0.f);
    ev.w += fmaxf(fmaf(en.w, rs.w, of.w), 0.f);
    oe[idx] = ev;
}

// ------------------------- launcher ---------------------------------------
extern "C" void kernel_launch(void* const* d_in, const int* in_sizes, int n_in,
                              void* d_out, int out_size) {
    const float* h     = (const float*)d_in[0];
    const float* e     = (const float*)d_in[1];
    const float* x     = (const float*)d_in[2];
    const int*   graph = (const int*)d_in[3];
    const float* Uw = (const float*)d_in[4],  *Ub = (const float*)d_in[5];
    const float* Vw = (const float*)d_in[6],  *Vb = (const float*)d_in[7];
    const float* Aw = (const float*)d_in[8],  *Ab = (const float*)d_in[9];
    const float* Bw = (const float*)d_in[10], *Bb = (const float*)d_in[11];
    const float* Cw = (const float*)d_in[12], *Cb = (const float*)d_in[13];
    const float* dwv = (const float*)d_in[14], *dbv = (const float*)d_in[15];
    const float* ewv = (const float*)d_in[16], *ebp = (const float*)d_in[17];
    const float* cp  = (const float*)d_in[18];
    const float* gh  = (const float*)d_in[19], *bh = (const float*)d_in[20];
    const float* ge  = (const float*)d_in[21], *be = (const float*)d_in[22];

    float* out_h = (float*)d_out;
    float* out_e = out_h + (size_t)BV * Hn;
    float* out_x = out_e + (size_t)NE * Hn;

    cudaFuncSetAttribute(k_main, cudaFuncAttributeMaxDynamicSharedMemorySize, SMEM_MAIN);

    k_prep<<<16, 256>>>(Cw);
    k_node_lin<<<64, 256>>>(h, Uw, Ub, Vw, Vb, Aw, Ab, Bw, Bb);
    k_main<<<4096, 256, SMEM_MAIN>>>(e, x, graph, Cb, dwv, dbv, ewv, out_e);
    k_stats1<<<64, 128>>>();
    k_stats2<<<1, 128>>>(gh, bh, ge, be);
    k_h_out<<<512, 256>>>(h, out_h);
    k_x_out<<<BV, 256>>>(x, cp, ebp, out_x);
    k_e_out<<<32768, 256>>>((const float4*)e, (float4*)out_e);
}